// round 3
// baseline (speedup 1.0000x reference)
#include <cuda_runtime.h>
#include <math.h>

// FeatureNormMagOnline: per-(b,c,f) EMA over time of |x|^2, normalize by sqrt.
// input  [B, C, T, F, 2] fp32
// weights[1, C, 1, F, 1], bias[1, C, 1, F, 1], alpha[1, C, F, 1], s_1[B, C, F, 1]
// out = concat( res[B,C,T,F,2].flatten(), s_last[B,C,F,1].flatten() )

#define B_ 16
#define C_ 2
#define T_ 1000
#define F_ 257

static const long long RES_ELEMS = (long long)B_ * C_ * T_ * F_ * 2;  // 16,448,000
static const int NSEQ = B_ * C_ * F_;                                  // 8224

__global__ void __launch_bounds__(32)
ema_norm_kernel(const float* __restrict__ in,
                const float* __restrict__ weights,
                const float* __restrict__ bias,
                const float* __restrict__ alpha,
                const float* __restrict__ s1,
                float* __restrict__ out,
                float* __restrict__ s_last_out)
{
    int idx = blockIdx.x * blockDim.x + threadIdx.x;
    if (idx >= NSEQ) return;

    // idx enumerates (b, c, f) with f fastest: idx = (b*C + c)*F + f
    int f  = idx % F_;
    int bc = idx / F_;           // b*C + c
    int c  = bc % C_;
    int cf = c * F_ + f;

    // a = sigmoid(alpha)
    float a   = 1.0f / (1.0f + __expf(-alpha[cf]));
    float oma = 1.0f - a;
    float w   = weights[cf];
    float bb  = bias[cf];
    float s   = s1[idx];

    const float2* __restrict__ inp  = (const float2*)in  + (size_t)bc * T_ * F_ + f;
    float2* __restrict__       outp = (float2*)out       + (size_t)bc * T_ * F_ + f;

    #pragma unroll 8
    for (int t = 0; t < T_; ++t) {
        float2 x = __ldcs(inp + (size_t)t * F_);
        float p  = fmaf(x.x, x.x, x.y * x.y);
        s = fmaf(oma, s, a * p);                 // EMA: s*(1-a) + p*a
        float sm  = sqrtf(s) + 1e-8f;
        float inv = __fdividef(w, sm);
        float2 o;
        o.x = fmaf(x.x, inv, bb);
        o.y = fmaf(x.y, inv, bb);
        __stcs(outp + (size_t)t * F_, o);
    }

    if (s_last_out) s_last_out[idx] = s;
}

extern "C" void kernel_launch(void* const* d_in, const int* in_sizes, int n_in,
                              void* d_out, int out_size)
{
    const float* in      = (const float*)d_in[0];
    const float* weights = (const float*)d_in[1];
    const float* bias    = (const float*)d_in[2];
    const float* alpha   = (const float*)d_in[3];
    const float* s1      = (const float*)d_in[4];

    float* out = (float*)d_out;
    // s_last appended after res, only if the output buffer actually has room.
    float* s_last = nullptr;
    if ((long long)out_size >= RES_ELEMS + NSEQ)
        s_last = out + RES_ELEMS;

    int nblocks = (NSEQ + 31) / 32;   // 257 blocks of 1 warp -> best SM spread
    ema_norm_kernel<<<nblocks, 32>>>(in, weights, bias, alpha, s1, out, s_last);
}

// round 6
// speedup vs baseline: 16.1785x; 16.1785x over previous
#include <cuda_runtime.h>
#include <math.h>

// FeatureNormMagOnline — chunked-scan decomposition.
// EMA s_t = (1-a)*s_{t-1} + a*p_t is a linear recurrence:
//   over a chunk of length L:  s_end = (1-a)^L * s_start + c_chunk
// Pass 1: per-(seq,chunk) partial c from zero start  (25x parallelism boost)
// Pass 2: per-(seq,chunk) reconstruct exact start state from partials (<=24 fma),
//         rescan chunk, write normalized output. Input re-read hits L2.

#define B_ 16
#define C_ 2
#define T_ 1000
#define F_ 257
#define BC_ (B_ * C_)      // 32
#define NCH 25
#define LCH 40             // NCH * LCH == T_

static const long long RES_ELEMS = (long long)B_ * C_ * T_ * F_ * 2;  // 16,448,000
static const int NSEQ = BC_ * F_;                                      // 8224

// scratch: per-chunk partial EMA sums, layout c[ch][bc][f] for coalesced access
__device__ float g_c[NCH * BC_ * F_];

__global__ void __launch_bounds__(288)
pass1_partials(const float* __restrict__ in,
               const float* __restrict__ alpha)
{
    int f = threadIdx.x;
    if (f >= F_) return;
    int bcch = blockIdx.x;         // bc * NCH + ch
    int ch = bcch % NCH;
    int bc = bcch / NCH;
    int c  = bc % C_;

    float a   = 1.0f / (1.0f + __expf(-alpha[c * F_ + f]));
    float oma = 1.0f - a;

    const float2* __restrict__ inp =
        (const float2*)in + ((size_t)bc * T_ + (size_t)ch * LCH) * F_ + f;

    float s = 0.0f;
    #pragma unroll
    for (int tb = 0; tb < LCH; tb += 8) {
        float2 x[8];
        #pragma unroll
        for (int k = 0; k < 8; ++k)              // batched: 8 loads in flight
            x[k] = inp[(size_t)(tb + k) * F_];
        #pragma unroll
        for (int k = 0; k < 8; ++k) {
            float p = fmaf(x[k].x, x[k].x, x[k].y * x[k].y);
            s = fmaf(oma, s, a * p);
        }
    }
    g_c[(ch * BC_ + bc) * F_ + f] = s;
}

__global__ void __launch_bounds__(288)
pass2_scan_out(const float* __restrict__ in,
               const float* __restrict__ weights,
               const float* __restrict__ bias,
               const float* __restrict__ alpha,
               const float* __restrict__ s1,
               float* __restrict__ out,
               float* __restrict__ s_last_out)
{
    int f = threadIdx.x;
    if (f >= F_) return;
    int bcch = blockIdx.x;
    int ch = bcch % NCH;
    int bc = bcch / NCH;
    int c  = bc % C_;
    int cf = c * F_ + f;

    float a   = 1.0f / (1.0f + __expf(-alpha[cf]));
    float oma = 1.0f - a;
    float w   = weights[cf];
    float bb  = bias[cf];

    // reconstruct exact start state for this chunk from the partials
    float s = s1[bc * F_ + f];
    float omaL = powf(oma, (float)LCH);
    for (int i = 0; i < ch; ++i)
        s = fmaf(omaL, s, g_c[(i * BC_ + bc) * F_ + f]);

    const float2* __restrict__ inp =
        (const float2*)in + ((size_t)bc * T_ + (size_t)ch * LCH) * F_ + f;
    float2* __restrict__ outp =
        (float2*)out      + ((size_t)bc * T_ + (size_t)ch * LCH) * F_ + f;

    #pragma unroll
    for (int tb = 0; tb < LCH; tb += 8) {
        float2 x[8];
        #pragma unroll
        for (int k = 0; k < 8; ++k)
            x[k] = inp[(size_t)(tb + k) * F_];
        float2 o[8];
        #pragma unroll
        for (int k = 0; k < 8; ++k) {
            float p = fmaf(x[k].x, x[k].x, x[k].y * x[k].y);
            s = fmaf(oma, s, a * p);
            float inv = __fdividef(w, sqrtf(s) + 1e-8f);
            o[k].x = fmaf(x[k].x, inv, bb);
            o[k].y = fmaf(x[k].y, inv, bb);
        }
        #pragma unroll
        for (int k = 0; k < 8; ++k)
            __stcs(outp + (size_t)(tb + k) * F_, o[k]);
    }

    if (ch == NCH - 1 && s_last_out)
        s_last_out[bc * F_ + f] = s;
}

extern "C" void kernel_launch(void* const* d_in, const int* in_sizes, int n_in,
                              void* d_out, int out_size)
{
    const float* in      = (const float*)d_in[0];
    const float* weights = (const float*)d_in[1];
    const float* bias    = (const float*)d_in[2];
    const float* alpha   = (const float*)d_in[3];
    const float* s1      = (const float*)d_in[4];

    float* out = (float*)d_out;
    float* s_last = nullptr;
    if ((long long)out_size >= RES_ELEMS + NSEQ)
        s_last = out + RES_ELEMS;

    dim3 grid(BC_ * NCH);   // 800 blocks
    dim3 block(288);        // f fastest; 9 warps, f<257 guard

    pass1_partials<<<grid, block>>>(in, alpha);
    pass2_scan_out<<<grid, block>>>(in, weights, bias, alpha, s1, out, s_last);
}